// round 8
// baseline (speedup 1.0000x reference)
#include <cuda_runtime.h>
#include <math.h>
#include <stdint.h>

#define NB   4
#define SEQ  2048
#define HID  1024
#define FAC  256
#define NHD  16
#define DK   64
#define ROWS (NB*SEQ)   /* 8192 */
#define BH   (NB*NHD)   /* 64   */

/* linear tiling: 128x128 block, 8 warps of 32x64 */
#define BM 128
#define BN 128
#define BK 32
#define LDA  36
#define LDBN 36

/* flash geometry */
#define KT   32          /* keys per chunk */
#define NCH  (SEQ/KT)    /* 64 */
#define LDQ  68
#define LDK  68
#define LDV  36
#define OFF_Q   0                         /* 128*LDQ; reused as P after prologue */
#define OFF_K   (128*LDQ)                 /* 8704  */
#define OFF_V   (OFF_K + 2*KT*LDK)        /* 13056 */
#define OFF_MB  (OFF_V + 2*DK*LDV)        /* 17664 */
#define FLASH_FLOATS (OFF_MB + 2*KT)
#define FLASH_SMEM   (FLASH_FLOATS*4)

/* ---------------- scratch ------------------------------------------------ */
__device__ float g_q  [ROWS*HID];
__device__ float g_k  [ROWS*HID];
__device__ float g_vt [BH*DK*SEQ];   /* V transposed: [bh][d][token] */
__device__ float g_h  [ROWS*FAC];
__device__ float g_cv [ROWS*HID];

/* ---------------- helpers ------------------------------------------------ */
__device__ __forceinline__ float tf32r(float x) {
    uint32_t u;
    asm("cvt.rna.tf32.f32 %0, %1;" : "=r"(u) : "f"(x));
    return __uint_as_float(u);
}
__device__ __forceinline__ float4 cvt4(float4 v) {
    v.x = tf32r(v.x); v.y = tf32r(v.y); v.z = tf32r(v.z); v.w = tf32r(v.w);
    return v;
}
__device__ __forceinline__ void mma_tf32(float c[4], const uint32_t a[4], const uint32_t b[2]) {
    asm volatile(
        "mma.sync.aligned.m16n8k8.row.col.f32.tf32.tf32.f32 "
        "{%0,%1,%2,%3}, {%4,%5,%6,%7}, {%8,%9}, {%0,%1,%2,%3};"
        : "+f"(c[0]), "+f"(c[1]), "+f"(c[2]), "+f"(c[3])
        : "r"(a[0]), "r"(a[1]), "r"(a[2]), "r"(a[3]), "r"(b[0]), "r"(b[1]));
}
__device__ __forceinline__ void ldsm4(uint32_t f[4], uint32_t addr) {
    asm volatile("ldmatrix.sync.aligned.m8n8.x4.shared.b16 {%0,%1,%2,%3}, [%4];"
        : "=r"(f[0]), "=r"(f[1]), "=r"(f[2]), "=r"(f[3]) : "r"(addr));
}
__device__ __forceinline__ uint32_t smem_u32(const void* p) {
    return (uint32_t)__cvta_generic_to_shared(p);
}
__device__ __forceinline__ void cpa16(uint32_t dst, const void* src) {
    asm volatile("cp.async.cg.shared.global [%0], [%1], 16;" :: "r"(dst), "l"(src));
}
#define CPA_COMMIT() asm volatile("cp.async.commit_group;" ::: "memory")
#define CPA_WAIT0()  asm volatile("cp.async.wait_group 0;" ::: "memory")

__device__ __forceinline__ uint32_t frag_base_m(uint32_t base, int row0, int lane, int ld) {
    int lr = lane & 7, sel = lane >> 3;
    int row = row0 + lr + ((sel & 1) << 3);
    int col = (sel & 2) << 1;
    return base + (uint32_t)(row*ld + col)*4u;
}
__device__ __forceinline__ uint32_t frag_base_n(uint32_t base, int n0, int lane, int ld) {
    int lr = lane & 7, sel = lane >> 3;
    int row = n0 + lr + ((sel & 2) << 2);
    int col = (sel & 1) << 2;
    return base + (uint32_t)(row*ld + col)*4u;
}

/* =================== TF32 linear =========================================
   128x128 block, warp tile 32x64.
   act: 0 = bias; 1 = bias+leaky(0.2); 2 = bias+tf32 round;
        3 = bias+tf32 round + TRANSPOSED store into Vt[bh][d][token]       */
__global__ void __launch_bounds__(256, 2) linear_tc(
    const float* __restrict__ A, const float* __restrict__ W,
    const float* __restrict__ bias, float* __restrict__ C,
    int M, int N, int K, int act)
{
    __shared__ __align__(16) float As[BM][LDA];
    __shared__ __align__(16) float Bs[BN][LDBN];

    const int tid = threadIdx.x;
    const int row0 = blockIdx.x * BM;
    const int col0 = blockIdx.y * BN;

    const int arow = tid >> 3, acol = (tid & 7) << 2;      /* A: 32 rows x 32k per pass */
    const int bn = tid & 127, bkg0 = tid >> 7;             /* B: n-major writer */

    const int wid = tid >> 5, lane = tid & 31;
    const int wm = (wid & 3) * 32, wn = (wid >> 2) * 64;
    const int r = lane >> 2, cq = lane & 3;

    const uint32_t smA = smem_u32(&As[0][0]);
    const uint32_t smB = smem_u32(&Bs[0][0]);
    const uint32_t aB0 = frag_base_m(smA, wm,      lane, LDA);
    const uint32_t aB1 = frag_base_m(smA, wm + 16, lane, LDA);
    uint32_t bB[4];
#pragma unroll
    for (int g = 0; g < 4; g++)
        bB[g] = frag_base_n(smB, wn + g*16, lane, LDBN);

    float acc[2][8][4];
#pragma unroll
    for (int mt = 0; mt < 2; mt++)
#pragma unroll
        for (int nt = 0; nt < 8; nt++)
#pragma unroll
            for (int i = 0; i < 4; i++) acc[mt][nt][i] = 0.f;

    float4 pa[4];
    float  pb[4][4];
    const int nch = K / BK;

#pragma unroll
    for (int p = 0; p < 4; p++)
        pa[p] = *(const float4*)(A + (size_t)(row0 + arow + 32*p)*K + acol);
#pragma unroll
    for (int i = 0; i < 4; i++) {
        int kg = bkg0 + 2*i;
#pragma unroll
        for (int j = 0; j < 4; j++)
            pb[i][j] = W[(size_t)(kg*4 + j)*N + col0 + bn];
    }

    for (int c = 0; c < nch; c++) {
#pragma unroll
        for (int p = 0; p < 4; p++)
            *(float4*)&As[arow + 32*p][acol] = cvt4(pa[p]);
#pragma unroll
        for (int i = 0; i < 4; i++) {
            int kg = bkg0 + 2*i;
            float4 t = make_float4(pb[i][0], pb[i][1], pb[i][2], pb[i][3]);
            *(float4*)&Bs[bn][kg*4] = cvt4(t);
        }
        __syncthreads();

        if (c + 1 < nch) {
            int k0 = (c + 1) * BK;
#pragma unroll
            for (int p = 0; p < 4; p++)
                pa[p] = *(const float4*)(A + (size_t)(row0 + arow + 32*p)*K + k0 + acol);
#pragma unroll
            for (int i = 0; i < 4; i++) {
                int kg = bkg0 + 2*i;
#pragma unroll
                for (int j = 0; j < 4; j++)
                    pb[i][j] = W[(size_t)(k0 + kg*4 + j)*N + col0 + bn];
            }
        }

#pragma unroll
        for (int kk = 0; kk < BK; kk += 8) {
            uint32_t af0[4], af1[4];
            ldsm4(af0, aB0 + kk*4);
            ldsm4(af1, aB1 + kk*4);
#pragma unroll
            for (int g = 0; g < 4; g++) {
                uint32_t bq[4];
                ldsm4(bq, bB[g] + kk*4);
                mma_tf32(acc[0][2*g    ], af0, &bq[0]);
                mma_tf32(acc[0][2*g + 1], af0, &bq[2]);
                mma_tf32(acc[1][2*g    ], af1, &bq[0]);
                mma_tf32(acc[1][2*g + 1], af1, &bq[2]);
            }
        }
        __syncthreads();
    }

#pragma unroll
    for (int mt = 0; mt < 2; mt++)
#pragma unroll
        for (int nt = 0; nt < 8; nt++) {
            int col = col0 + wn + nt*8 + cq*2;
            float b0 = bias[col], b1 = bias[col + 1];
#pragma unroll
            for (int hrow = 0; hrow < 2; hrow++) {
                int row = row0 + wm + mt*16 + r + hrow*8;
                float v0 = acc[mt][nt][hrow*2 + 0] + b0;
                float v1 = acc[mt][nt][hrow*2 + 1] + b1;
                if (act == 1) {
                    v0 = (v0 > 0.f) ? v0 : 0.2f*v0;
                    v1 = (v1 > 0.f) ? v1 : 0.2f*v1;
                } else if (act >= 2) {
                    v0 = tf32r(v0); v1 = tf32r(v1);
                }
                if (act == 3) {
                    int bb = row >> 11, token = row & (SEQ - 1);
                    int h0 = col >> 6, d0 = col & 63;
                    float* dst = C + ((size_t)(bb*NHD + h0)*DK + d0)*SEQ + token;
                    dst[0]   = v0;
                    dst[SEQ] = v1;
                } else {
                    *(float2*)&C[(size_t)row*N + col] = make_float2(v0, v1);
                }
            }
        }
}

/* =================== Flash attention v3 ==================================
   Q fragments register-resident (loop-invariant); Qs smem reused as P.    */
__global__ void __launch_bounds__(256, 2) flash_tc(
    const float* __restrict__ Q, const float* __restrict__ K,
    const float* __restrict__ Vt, const int* __restrict__ mask,
    float* __restrict__ Cv)
{
    extern __shared__ __align__(16) float sm[];
    const uint32_t smBase = smem_u32(sm);
    const uint32_t smQ = smBase + OFF_Q*4u;          /* aliased: P lives here after prologue */
    const uint32_t smK[2] = { smBase + OFF_K*4u, smBase + (OFF_K + KT*LDK)*4u };
    const uint32_t smV[2] = { smBase + OFF_V*4u, smBase + (OFF_V + DK*LDV)*4u };
    const uint32_t smM = smBase + OFF_MB*4u;
    const int* MBI = (const int*)(sm + OFF_MB);

    const int bh = blockIdx.y;
    const int b = bh >> 4, h = bh & 15;
    const int i0 = blockIdx.x * 128;
    const float* Qp  = Q  + (size_t)b*SEQ*HID + h*DK;
    const float* Kp  = K  + (size_t)b*SEQ*HID + h*DK;
    const float* Vtp = Vt + (size_t)bh*DK*SEQ;
    const int* mrow = mask + b*SEQ;
    float* Cp = Cv + (size_t)b*SEQ*HID + h*DK;

    const int tid = threadIdx.x;
    const int wid = tid >> 5, lane = tid & 31;
    const int wm = wid * 16;
    const int r = lane >> 2, cq = lane & 3;

    /* ---- prologue: async-load Q tile + chunk 0 ---- */
#pragma unroll
    for (int p = 0; p < 8; p++) {
        int idx = p*256 + tid;
        int row = idx >> 4, u = idx & 15;
        cpa16(smQ + (uint32_t)(row*LDQ + u*4)*4u,
              Qp + (size_t)(i0 + row)*HID + u*4);
    }
#pragma unroll
    for (int p = 0; p < 2; p++) {
        int idx = p*256 + tid;
        int krow = idx >> 4, ku = idx & 15;
        cpa16(smK[0] + (uint32_t)(krow*LDK + ku*4)*4u,
              Kp + (size_t)krow*HID + ku*4);
        int vrow = idx >> 3, vu = idx & 7;
        cpa16(smV[0] + (uint32_t)(vrow*LDV + vu*4)*4u,
              Vtp + (size_t)vrow*SEQ + vu*4);
    }
    if (tid < 8) cpa16(smM + (uint32_t)(tid*4)*4u, mrow + tid*4);
    CPA_COMMIT();

    const uint32_t aQ = frag_base_m(smQ, wm, lane, LDQ);
    const uint32_t aP = aQ;                               /* same region, same layout */
    uint32_t bKf[2][2], bVf[2][4];
#pragma unroll
    for (int buf = 0; buf < 2; buf++) {
#pragma unroll
        for (int g = 0; g < 2; g++) bKf[buf][g] = frag_base_n(smK[buf], g*16, lane, LDK);
#pragma unroll
        for (int g = 0; g < 4; g++) bVf[buf][g] = frag_base_n(smV[buf], g*16, lane, LDV);
    }

    CPA_WAIT0();
    __syncthreads();          /* Q + chunk0 resident */

    /* hoist Q fragments to registers */
    uint32_t qf[8][4];
#pragma unroll
    for (int s = 0; s < 8; s++) ldsm4(qf[s], aQ + s*32);
    __syncthreads();          /* all warps done reading Qs; region now P */

    float acc_o[8][4];
#pragma unroll
    for (int nt = 0; nt < 8; nt++)
#pragma unroll
        for (int i = 0; i < 4; i++) acc_o[nt][i] = 0.f;
    float m_st[2] = {-1e20f, -1e20f};
    float l_st[2] = {0.f, 0.f};

    for (int c = 0; c < NCH; c++) {
        const int cur = c & 1, nxt = cur ^ 1;

        if (c + 1 < NCH) {
            const size_t k0 = (size_t)(c + 1) * KT;
#pragma unroll
            for (int p = 0; p < 2; p++) {
                int idx = p*256 + tid;
                int krow = idx >> 4, ku = idx & 15;
                cpa16(smK[nxt] + (uint32_t)(krow*LDK + ku*4)*4u,
                      Kp + (k0 + krow)*HID + ku*4);
                int vrow = idx >> 3, vu = idx & 7;
                cpa16(smV[nxt] + (uint32_t)(vrow*LDV + vu*4)*4u,
                      Vtp + (size_t)vrow*SEQ + k0 + vu*4);
            }
            if (tid < 8) cpa16(smM + (uint32_t)(nxt*KT + tid*4)*4u, mrow + k0 + tid*4);
            CPA_COMMIT();
        }

        /* S = Q @ K^T : 16 rows x 32 keys per warp, Q from registers */
        float acc_s[4][4];
#pragma unroll
        for (int nt = 0; nt < 4; nt++)
#pragma unroll
            for (int i = 0; i < 4; i++) acc_s[nt][i] = 0.f;
#pragma unroll
        for (int s = 0; s < 8; s++) {
#pragma unroll
            for (int g = 0; g < 2; g++) {
                uint32_t bq[4];
                ldsm4(bq, bKf[cur][g] + s*32);
                mma_tf32(acc_s[2*g    ], qf[s], &bq[0]);
                mma_tf32(acc_s[2*g + 1], qf[s], &bq[2]);
            }
        }

        /* online softmax (warp-local rows) */
        const int* mi = MBI + cur*KT;
        float bias2[4][2];
#pragma unroll
        for (int nt = 0; nt < 4; nt++) {
            int j = nt*8 + cq*2;
            bias2[nt][0] = mi[j]     ? 0.f : -1e20f;
            bias2[nt][1] = mi[j + 1] ? 0.f : -1e20f;
        }
        float alpha[2];
#pragma unroll
        for (int rr = 0; rr < 2; rr++) {
            float mx = -3.4e38f;
#pragma unroll
            for (int nt = 0; nt < 4; nt++)
#pragma unroll
                for (int cc = 0; cc < 2; cc++) {
                    float s = acc_s[nt][rr*2+cc] * 0.125f + bias2[nt][cc];
                    acc_s[nt][rr*2+cc] = s;
                    mx = fmaxf(mx, s);
                }
            mx = fmaxf(mx, __shfl_xor_sync(0xffffffffu, mx, 1));
            mx = fmaxf(mx, __shfl_xor_sync(0xffffffffu, mx, 2));
            float m_new = fmaxf(m_st[rr], mx);
            float a = __expf(m_st[rr] - m_new);
            m_st[rr] = m_new;
            alpha[rr] = a;
            float lsum = 0.f;
#pragma unroll
            for (int nt = 0; nt < 4; nt++)
#pragma unroll
                for (int cc = 0; cc < 2; cc++) {
                    float p = __expf(acc_s[nt][rr*2+cc] - m_new);
                    acc_s[nt][rr*2+cc] = p;
                    lsum += p;
                }
            l_st[rr] = l_st[rr]*a + lsum;
        }
#pragma unroll
        for (int nt = 0; nt < 8; nt++)
#pragma unroll
            for (int i = 0; i < 4; i++) acc_o[nt][i] *= alpha[i>>1];

        /* write P (warp-private rows of reused Q region, stride LDQ) */
#pragma unroll
        for (int rr = 0; rr < 2; rr++) {
            int prow = wm + rr*8 + r;
#pragma unroll
            for (int nt = 0; nt < 4; nt++)
                *(float2*)&sm[OFF_Q + prow*LDQ + nt*8 + cq*2] =
                    make_float2(tf32r(acc_s[nt][rr*2+0]), tf32r(acc_s[nt][rr*2+1]));
        }
        __syncwarp();

        /* O += P @ V : B from transposed V via ldmatrix */
#pragma unroll
        for (int kk = 0; kk < KT; kk += 8) {
            uint32_t af[4];
            ldsm4(af, aP + kk*4);
#pragma unroll
            for (int g = 0; g < 4; g++) {
                uint32_t bv[4];
                ldsm4(bv, bVf[cur][g] + kk*4);
                mma_tf32(acc_o[2*g    ], af, &bv[0]);
                mma_tf32(acc_o[2*g + 1], af, &bv[2]);
            }
        }

        if (c + 1 < NCH) {
            CPA_WAIT0();
            __syncthreads();   /* next chunk resident; all warps done with cur */
        }
    }

    /* epilogue */
    float inv2[2];
#pragma unroll
    for (int rr = 0; rr < 2; rr++) {
        float lt = l_st[rr];
        lt += __shfl_xor_sync(0xffffffffu, lt, 1);
        lt += __shfl_xor_sync(0xffffffffu, lt, 2);
        inv2[rr] = 1.f / lt;
    }
#pragma unroll
    for (int nt = 0; nt < 8; nt++) {
        int col = nt*8 + cq*2;
#pragma unroll
        for (int rr = 0; rr < 2; rr++) {
            int row = i0 + wm + rr*8 + r;
            *(float2*)&Cp[(size_t)row*HID + col] =
                make_float2(acc_o[nt][rr*2+0]*inv2[rr],
                            acc_o[nt][rr*2+1]*inv2[rr]);
        }
    }
}

/* ---------------- host orchestration ------------------------------------- */
extern "C" void kernel_launch(void* const* d_in, const int* in_sizes, int n_in,
                              void* d_out, int out_size)
{
    const float* query = (const float*)d_in[0];
    const float* key   = (const float*)d_in[1];
    const float* value = (const float*)d_in[2];
    const int*   mask  = (const int*)  d_in[3];
    const float* Wpq = (const float*)d_in[4],  *bpq = (const float*)d_in[5];
    const float* Wtq = (const float*)d_in[6],  *btq = (const float*)d_in[7];
    const float* Wpk = (const float*)d_in[8],  *bpk = (const float*)d_in[9];
    const float* Wtk = (const float*)d_in[10], *btk = (const float*)d_in[11];
    const float* Wpv = (const float*)d_in[12], *bpv = (const float*)d_in[13];
    const float* Wtv = (const float*)d_in[14], *btv = (const float*)d_in[15];
    const float* Wpo = (const float*)d_in[16], *bpo = (const float*)d_in[17];
    const float* Wto = (const float*)d_in[18], *bto = (const float*)d_in[19];
    float* out = (float*)d_out;

    float *q_, *k_, *vt_, *h_, *cv_;
    cudaGetSymbolAddress((void**)&q_,  g_q);
    cudaGetSymbolAddress((void**)&k_,  g_k);
    cudaGetSymbolAddress((void**)&vt_, g_vt);
    cudaGetSymbolAddress((void**)&h_,  g_h);
    cudaGetSymbolAddress((void**)&cv_, g_cv);

    cudaFuncSetAttribute(flash_tc, cudaFuncAttributeMaxDynamicSharedMemorySize,
                         FLASH_SMEM);

    dim3 blk(256);
    dim3 gproj(ROWS/BM, FAC/BN);   /* (64, 2)  */
    dim3 gtran(ROWS/BM, HID/BN);   /* (64, 8)  */

    linear_tc<<<gproj, blk>>>(query, Wpq, bpq, h_, ROWS, FAC, HID, 1);
    linear_tc<<<gtran, blk>>>(h_,    Wtq, btq, q_, ROWS, HID, FAC, 2);
    linear_tc<<<gproj, blk>>>(key,   Wpk, bpk, h_, ROWS, FAC, HID, 1);
    linear_tc<<<gtran, blk>>>(h_,    Wtk, btk, k_, ROWS, HID, FAC, 2);
    linear_tc<<<gproj, blk>>>(value, Wpv, bpv, h_, ROWS, FAC, HID, 1);
    linear_tc<<<gtran, blk>>>(h_,    Wtv, btv, vt_, ROWS, HID, FAC, 3);

    flash_tc<<<dim3(SEQ/128, BH), blk, FLASH_SMEM>>>(q_, k_, vt_, mask, cv_);

    linear_tc<<<gproj, blk>>>(cv_, Wpo, bpo, h_,  ROWS, FAC, HID, 1);
    linear_tc<<<gtran, blk>>>(h_,  Wto, bto, out, ROWS, HID, FAC, 0);
}

// round 9
// speedup vs baseline: 1.3422x; 1.3422x over previous
#include <cuda_runtime.h>
#include <math.h>
#include <stdint.h>

#define NB   4
#define SEQ  2048
#define HID  1024
#define FAC  256
#define NHD  16
#define DK   64
#define ROWS (NB*SEQ)   /* 8192 */
#define BH   (NB*NHD)   /* 64   */

/* linear tiling (R7 geometry): 128x64 block, 8 warps of 32x32 */
#define BM 128
#define BN 64
#define BK 32
#define LDA  36
#define LDBN 36
#define LIN_AS (BM*LDA)                    /* 4608 floats per stage */
#define LIN_BS (BN*LDBN)                   /* 2304 floats per stage */
#define LIN_FLOATS (2*LIN_AS + 2*LIN_BS)   /* 13824 */
#define LIN_SMEM (LIN_FLOATS*4)            /* 55296 B */

/* flash geometry (R7, unchanged) */
#define KT   32
#define NCH  (SEQ/KT)    /* 64 */
#define LDQ  68
#define LDK  68
#define LDV  36
#define LDP  36
#define OFF_Q   0
#define OFF_K   (128*LDQ)                 /* 8704  */
#define OFF_V   (OFF_K + 2*KT*LDK)        /* 13056 */
#define OFF_P   (OFF_V + 2*DK*LDV)        /* 17664 */
#define OFF_MB  (OFF_P + 128*LDP)         /* 22272 */
#define FLASH_FLOATS (OFF_MB + 2*KT)      /* 22336 */
#define FLASH_SMEM   (FLASH_FLOATS*4)     /* 89344 B */

/* ---------------- scratch ------------------------------------------------ */
__device__ float g_q  [ROWS*HID];
__device__ float g_k  [ROWS*HID];
__device__ float g_vt [BH*DK*SEQ];   /* V transposed: [bh][d][token] */
__device__ float g_h  [ROWS*FAC];
__device__ float g_cv [ROWS*HID];
__device__ float g_wt [8*HID*FAC];   /* rounded+transposed weights [N][K] */

/* ---------------- helpers ------------------------------------------------ */
__device__ __forceinline__ float tf32r(float x) {
    uint32_t u;
    asm("cvt.rna.tf32.f32 %0, %1;" : "=r"(u) : "f"(x));
    return __uint_as_float(u);
}
__device__ __forceinline__ float4 cvt4(float4 v) {
    v.x = tf32r(v.x); v.y = tf32r(v.y); v.z = tf32r(v.z); v.w = tf32r(v.w);
    return v;
}
__device__ __forceinline__ void mma_tf32(float c[4], const uint32_t a[4], const uint32_t b[2]) {
    asm volatile(
        "mma.sync.aligned.m16n8k8.row.col.f32.tf32.tf32.f32 "
        "{%0,%1,%2,%3}, {%4,%5,%6,%7}, {%8,%9}, {%0,%1,%2,%3};"
        : "+f"(c[0]), "+f"(c[1]), "+f"(c[2]), "+f"(c[3])
        : "r"(a[0]), "r"(a[1]), "r"(a[2]), "r"(a[3]), "r"(b[0]), "r"(b[1]));
}
__device__ __forceinline__ void ldsm4(uint32_t f[4], uint32_t addr) {
    asm volatile("ldmatrix.sync.aligned.m8n8.x4.shared.b16 {%0,%1,%2,%3}, [%4];"
        : "=r"(f[0]), "=r"(f[1]), "=r"(f[2]), "=r"(f[3]) : "r"(addr));
}
__device__ __forceinline__ uint32_t smem_u32(const void* p) {
    return (uint32_t)__cvta_generic_to_shared(p);
}
__device__ __forceinline__ void cpa16(uint32_t dst, const void* src) {
    asm volatile("cp.async.cg.shared.global [%0], [%1], 16;" :: "r"(dst), "l"(src));
}
#define CPA_COMMIT() asm volatile("cp.async.commit_group;" ::: "memory")
#define CPA_WAIT0()  asm volatile("cp.async.wait_group 0;" ::: "memory")

__device__ __forceinline__ uint32_t frag_base_m(uint32_t base, int row0, int lane, int ld) {
    int lr = lane & 7, sel = lane >> 3;
    int row = row0 + lr + ((sel & 1) << 3);
    int col = (sel & 2) << 1;
    return base + (uint32_t)(row*ld + col)*4u;
}
__device__ __forceinline__ uint32_t frag_base_n(uint32_t base, int n0, int lane, int ld) {
    int lr = lane & 7, sel = lane >> 3;
    int row = n0 + lr + ((sel & 2) << 2);
    int col = (sel & 1) << 2;
    return base + (uint32_t)(row*ld + col)*4u;
}

#define MMA_CHUNK(aB0, aB1, bB0, bB1, acc)                                    \
    _Pragma("unroll")                                                         \
    for (int kk = 0; kk < BK; kk += 8) {                                      \
        uint32_t af0[4], af1[4], bq0[4], bq1[4];                              \
        ldsm4(af0, (aB0) + kk*4);                                             \
        ldsm4(af1, (aB1) + kk*4);                                             \
        ldsm4(bq0, (bB0) + kk*4);                                             \
        ldsm4(bq1, (bB1) + kk*4);                                             \
        mma_tf32(acc[0][0], af0, &bq0[0]);                                    \
        mma_tf32(acc[0][1], af0, &bq0[2]);                                    \
        mma_tf32(acc[0][2], af0, &bq1[0]);                                    \
        mma_tf32(acc[0][3], af0, &bq1[2]);                                    \
        mma_tf32(acc[1][0], af1, &bq0[0]);                                    \
        mma_tf32(acc[1][1], af1, &bq0[2]);                                    \
        mma_tf32(acc[1][2], af1, &bq1[0]);                                    \
        mma_tf32(acc[1][3], af1, &bq1[2]);                                    \
    }

/* =================== weight prep: round + transpose ====================== */
struct WP { const float* w[8]; float* wt[8]; };

__global__ void __launch_bounds__(256) wprep(WP wp) {
    const int z = blockIdx.z;
    const int K = (z & 1) ? FAC : HID;
    const int N = (z & 1) ? HID : FAC;
    const int k0 = blockIdx.x * 32, n0 = blockIdx.y * 32;
    if (k0 >= K || n0 >= N) return;
    __shared__ float t[32][33];
    const float* W = wp.w[z];
    float* Wt = wp.wt[z];
    const int tx = threadIdx.x, ty = threadIdx.y;
#pragma unroll
    for (int i = 0; i < 4; i++)
        t[ty + 8*i][tx] = tf32r(W[(size_t)(k0 + ty + 8*i)*N + n0 + tx]);
    __syncthreads();
#pragma unroll
    for (int i = 0; i < 4; i++)
        Wt[(size_t)(n0 + ty + 8*i)*K + k0 + tx] = t[tx][ty + 8*i];
}

/* =================== TF32 linear, cp.async double-buffered ===============
   Wt is [N][K] pre-rounded tf32. aPre=1: A pre-rounded -> cp.async;
   aPre=0: A raw fp32 -> LDG + cvt + STS.
   act: 0 = bias; 1 = bias+leaky(0.2)+tf32 round; 2 = bias+tf32 round;
        3 = bias+tf32 round + transposed store into Vt[bh][d][token]       */
__global__ void __launch_bounds__(256, 3) linear_tc(
    const float* __restrict__ A, const float* __restrict__ Wt,
    const float* __restrict__ bias, float* __restrict__ C,
    int M, int N, int K, int act, int aPre)
{
    extern __shared__ __align__(16) float lsm[];
    const uint32_t smBase = smem_u32(lsm);
    const uint32_t smA[2] = { smBase, smBase + LIN_AS*4u };
    const uint32_t smB[2] = { smBase + 2u*LIN_AS*4u, smBase + (2u*LIN_AS + LIN_BS)*4u };

    const int tid = threadIdx.x;
    const int row0 = blockIdx.x * BM;
    const int col0 = blockIdx.y * BN;

    const int wid = tid >> 5, lane = tid & 31;
    const int wm = (wid >> 1) * 32, wn = (wid & 1) * 32;
    const int r = lane >> 2, cq = lane & 3;

    uint32_t aB0[2], aB1[2], bB0[2], bB1[2];
#pragma unroll
    for (int s = 0; s < 2; s++) {
        aB0[s] = frag_base_m(smA[s], wm,      lane, LDA);
        aB1[s] = frag_base_m(smA[s], wm + 16, lane, LDA);
        bB0[s] = frag_base_n(smB[s], wn,      lane, LDBN);
        bB1[s] = frag_base_n(smB[s], wn + 16, lane, LDBN);
    }

    float acc[2][4][4];
#pragma unroll
    for (int mt = 0; mt < 2; mt++)
#pragma unroll
        for (int nt = 0; nt < 4; nt++)
#pragma unroll
            for (int i = 0; i < 4; i++) acc[mt][nt][i] = 0.f;

    const int nch = K / BK;
    float4 pa[4];

    /* ---- prologue: stage 0 ---- */
    if (aPre) {
#pragma unroll
        for (int p = 0; p < 4; p++) {
            int idx = p*256 + tid;
            int arow = idx >> 3, ch = idx & 7;
            cpa16(smA[0] + (uint32_t)(arow*LDA + ch*4)*4u,
                  A + (size_t)(row0 + arow)*K + ch*4);
        }
    } else {
#pragma unroll
        for (int p = 0; p < 4; p++) {
            int idx = p*256 + tid;
            int arow = idx >> 3, ch = idx & 7;
            pa[p] = *(const float4*)(A + (size_t)(row0 + arow)*K + ch*4);
        }
    }
#pragma unroll
    for (int p = 0; p < 2; p++) {
        int idx = p*256 + tid;
        int brow = idx >> 3, ch = idx & 7;
        cpa16(smB[0] + (uint32_t)(brow*LDBN + ch*4)*4u,
              Wt + (size_t)(col0 + brow)*K + ch*4);
    }
    CPA_COMMIT();

    for (int c = 0; c < nch; c++) {
        const int cur = c & 1, nxt = cur ^ 1;

        CPA_WAIT0();
        if (!aPre) {
#pragma unroll
            for (int p = 0; p < 4; p++) {
                int idx = p*256 + tid;
                int arow = idx >> 3, ch = idx & 7;
                *(float4*)&lsm[cur*LIN_AS + arow*LDA + ch*4] = cvt4(pa[p]);
            }
        }
        __syncthreads();

        if (c + 1 < nch) {
            const int k0 = (c + 1) * BK;
            if (aPre) {
#pragma unroll
                for (int p = 0; p < 4; p++) {
                    int idx = p*256 + tid;
                    int arow = idx >> 3, ch = idx & 7;
                    cpa16(smA[nxt] + (uint32_t)(arow*LDA + ch*4)*4u,
                          A + (size_t)(row0 + arow)*K + k0 + ch*4);
                }
            } else {
#pragma unroll
                for (int p = 0; p < 4; p++) {
                    int idx = p*256 + tid;
                    int arow = idx >> 3, ch = idx & 7;
                    pa[p] = *(const float4*)(A + (size_t)(row0 + arow)*K + k0 + ch*4);
                }
            }
#pragma unroll
            for (int p = 0; p < 2; p++) {
                int idx = p*256 + tid;
                int brow = idx >> 3, ch = idx & 7;
                cpa16(smB[nxt] + (uint32_t)(brow*LDBN + ch*4)*4u,
                      Wt + (size_t)(col0 + brow)*K + k0 + ch*4);
            }
            CPA_COMMIT();
        }

        MMA_CHUNK(aB0[cur], aB1[cur], bB0[cur], bB1[cur], acc);
    }

#pragma unroll
    for (int mt = 0; mt < 2; mt++)
#pragma unroll
        for (int nt = 0; nt < 4; nt++) {
            int col = col0 + wn + nt*8 + cq*2;
            float b0 = bias[col], b1 = bias[col + 1];
#pragma unroll
            for (int hrow = 0; hrow < 2; hrow++) {
                int row = row0 + wm + mt*16 + r + hrow*8;
                float v0 = acc[mt][nt][hrow*2 + 0] + b0;
                float v1 = acc[mt][nt][hrow*2 + 1] + b1;
                if (act == 1) {
                    v0 = (v0 > 0.f) ? v0 : 0.2f*v0;
                    v1 = (v1 > 0.f) ? v1 : 0.2f*v1;
                    v0 = tf32r(v0); v1 = tf32r(v1);
                } else if (act >= 2) {
                    v0 = tf32r(v0); v1 = tf32r(v1);
                }
                if (act == 3) {
                    int bb = row >> 11, token = row & (SEQ - 1);
                    int h0 = col >> 6, d0 = col & 63;
                    float* dst = C + ((size_t)(bb*NHD + h0)*DK + d0)*SEQ + token;
                    dst[0]   = v0;
                    dst[SEQ] = v1;
                } else {
                    *(float2*)&C[(size_t)row*N + col] = make_float2(v0, v1);
                }
            }
        }
}

/* =================== Flash attention (R7, unchanged) ===================== */
__global__ void __launch_bounds__(256, 2) flash_tc(
    const float* __restrict__ Q, const float* __restrict__ K,
    const float* __restrict__ Vt, const int* __restrict__ mask,
    float* __restrict__ Cv)
{
    extern __shared__ __align__(16) float sm[];
    const uint32_t smBase = smem_u32(sm);
    const uint32_t smQ = smBase + OFF_Q*4u;
    const uint32_t smK[2] = { smBase + OFF_K*4u, smBase + (OFF_K + KT*LDK)*4u };
    const uint32_t smV[2] = { smBase + OFF_V*4u, smBase + (OFF_V + DK*LDV)*4u };
    const uint32_t smM = smBase + OFF_MB*4u;
    const int* MBI = (const int*)(sm + OFF_MB);

    const int bh = blockIdx.y;
    const int b = bh >> 4, h = bh & 15;
    const int i0 = blockIdx.x * 128;
    const float* Qp  = Q  + (size_t)b*SEQ*HID + h*DK;
    const float* Kp  = K  + (size_t)b*SEQ*HID + h*DK;
    const float* Vtp = Vt + (size_t)bh*DK*SEQ;
    const int* mrow = mask + b*SEQ;
    float* Cp = Cv + (size_t)b*SEQ*HID + h*DK;

    const int tid = threadIdx.x;
    const int wid = tid >> 5, lane = tid & 31;
    const int wm = wid * 16;
    const int r = lane >> 2, cq = lane & 3;

#pragma unroll
    for (int p = 0; p < 8; p++) {
        int idx = p*256 + tid;
        int row = idx >> 4, u = idx & 15;
        cpa16(smQ + (uint32_t)(row*LDQ + u*4)*4u,
              Qp + (size_t)(i0 + row)*HID + u*4);
    }
#pragma unroll
    for (int p = 0; p < 2; p++) {
        int idx = p*256 + tid;
        int krow = idx >> 4, ku = idx & 15;
        cpa16(smK[0] + (uint32_t)(krow*LDK + ku*4)*4u,
              Kp + (size_t)krow*HID + ku*4);
        int vrow = idx >> 3, vu = idx & 7;
        cpa16(smV[0] + (uint32_t)(vrow*LDV + vu*4)*4u,
              Vtp + (size_t)vrow*SEQ + vu*4);
    }
    if (tid < 8) cpa16(smM + (uint32_t)(tid*4)*4u, mrow + tid*4);
    CPA_COMMIT();

    const uint32_t aQ = frag_base_m(smQ, wm, lane, LDQ);
    const uint32_t aP = frag_base_m(smBase + OFF_P*4u, wm, lane, LDP);
    uint32_t bKf[2][2], bVf[2][4];
#pragma unroll
    for (int buf = 0; buf < 2; buf++) {
#pragma unroll
        for (int g = 0; g < 2; g++) bKf[buf][g] = frag_base_n(smK[buf], g*16, lane, LDK);
#pragma unroll
        for (int g = 0; g < 4; g++) bVf[buf][g] = frag_base_n(smV[buf], g*16, lane, LDV);
    }

    float acc_o[8][4];
#pragma unroll
    for (int nt = 0; nt < 8; nt++)
#pragma unroll
        for (int i = 0; i < 4; i++) acc_o[nt][i] = 0.f;
    float m_st[2] = {-1e20f, -1e20f};
    float l_st[2] = {0.f, 0.f};

    for (int c = 0; c < NCH; c++) {
        const int cur = c & 1, nxt = cur ^ 1;

        CPA_WAIT0();
        __syncthreads();

        if (c + 1 < NCH) {
            const size_t k0 = (size_t)(c + 1) * KT;
#pragma unroll
            for (int p = 0; p < 2; p++) {
                int idx = p*256 + tid;
                int krow = idx >> 4, ku = idx & 15;
                cpa16(smK[nxt] + (uint32_t)(krow*LDK + ku*4)*4u,
                      Kp + (k0 + krow)*HID + ku*4);
                int vrow = idx >> 3, vu = idx & 7;
                cpa16(smV[nxt] + (uint32_t)(vrow*LDV + vu*4)*4u,
                      Vtp + (size_t)vrow*SEQ + k0 + vu*4);
            }
            if (tid < 8) cpa16(smM + (uint32_t)(nxt*KT + tid*4)*4u, mrow + k0 + tid*4);
            CPA_COMMIT();
        }

        float acc_s[4][4];
#pragma unroll
        for (int nt = 0; nt < 4; nt++)
#pragma unroll
            for (int i = 0; i < 4; i++) acc_s[nt][i] = 0.f;
#pragma unroll
        for (int kk = 0; kk < DK; kk += 8) {
            uint32_t af[4];
            ldsm4(af, aQ + kk*4);
#pragma unroll
            for (int g = 0; g < 2; g++) {
                uint32_t bq[4];
                ldsm4(bq, bKf[cur][g] + kk*4);
                mma_tf32(acc_s[2*g    ], af, &bq[0]);
                mma_tf32(acc_s[2*g + 1], af, &bq[2]);
            }
        }

        const int* mi = MBI + cur*KT;
        float bias2[4][2];
#pragma unroll
        for (int nt = 0; nt < 4; nt++) {
            int j = nt*8 + cq*2;
            bias2[nt][0] = mi[j]     ? 0.f : -1e20f;
            bias2[nt][1] = mi[j + 1] ? 0.f : -1e20f;
        }
        float alpha[2];
#pragma unroll
        for (int rr = 0; rr < 2; rr++) {
            float mx = -3.4e38f;
#pragma unroll
            for (int nt = 0; nt < 4; nt++)
#pragma unroll
                for (int cc = 0; cc < 2; cc++) {
                    float s = acc_s[nt][rr*2+cc] * 0.125f + bias2[nt][cc];
                    acc_s[nt][rr*2+cc] = s;
                    mx = fmaxf(mx, s);
                }
            mx = fmaxf(mx, __shfl_xor_sync(0xffffffffu, mx, 1));
            mx = fmaxf(mx, __shfl_xor_sync(0xffffffffu, mx, 2));
            float m_new = fmaxf(m_st[rr], mx);
            float a = __expf(m_st[rr] - m_new);
            m_st[rr] = m_new;
            alpha[rr] = a;
            float lsum = 0.f;
#pragma unroll
            for (int nt = 0; nt < 4; nt++)
#pragma unroll
                for (int cc = 0; cc < 2; cc++) {
                    float p = __expf(acc_s[nt][rr*2+cc] - m_new);
                    acc_s[nt][rr*2+cc] = p;
                    lsum += p;
                }
            l_st[rr] = l_st[rr]*a + lsum;
        }
#pragma unroll
        for (int nt = 0; nt < 8; nt++)
#pragma unroll
            for (int i = 0; i < 4; i++) acc_o[nt][i] *= alpha[i>>1];

#pragma unroll
        for (int rr = 0; rr < 2; rr++) {
            int prow = wm + rr*8 + r;
#pragma unroll
            for (int nt = 0; nt < 4; nt++)
                *(float2*)&sm[OFF_P + prow*LDP + nt*8 + cq*2] =
                    make_float2(tf32r(acc_s[nt][rr*2+0]), tf32r(acc_s[nt][rr*2+1]));
        }
        __syncwarp();

#pragma unroll
        for (int kk = 0; kk < KT; kk += 8) {
            uint32_t af[4];
            ldsm4(af, aP + kk*4);
#pragma unroll
            for (int g = 0; g < 4; g++) {
                uint32_t bv[4];
                ldsm4(bv, bVf[cur][g] + kk*4);
                mma_tf32(acc_o[2*g    ], af, &bv[0]);
                mma_tf32(acc_o[2*g + 1], af, &bv[2]);
            }
        }
    }

    float inv2[2];
#pragma unroll
    for (int rr = 0; rr < 2; rr++) {
        float lt = l_st[rr];
        lt += __shfl_xor_sync(0xffffffffu, lt, 1);
        lt += __shfl_xor_sync(0xffffffffu, lt, 2);
        inv2[rr] = 1.f / lt;
    }
#pragma unroll
    for (int nt = 0; nt < 8; nt++) {
        int col = nt*8 + cq*2;
#pragma unroll
        for (int rr = 0; rr < 2; rr++) {
            int row = i0 + wm + rr*8 + r;
            *(float2*)&Cp[(size_t)row*HID + col] =
                make_float2(acc_o[nt][rr*2+0]*inv2[rr],
                            acc_o[nt][rr*2+1]*inv2[rr]);
        }
    }
}

/* ---------------- host orchestration ------------------------------------- */
extern "C" void kernel_launch(void* const* d_in, const int* in_sizes, int n_in,
                              void* d_out, int out_size)
{
    const float* query = (const float*)d_in[0];
    const float* key   = (const float*)d_in[1];
    const float* value = (const float*)d_in[2];
    const int*   mask  = (const int*)  d_in[3];
    const float* bpq = (const float*)d_in[5];
    const float* btq = (const float*)d_in[7];
    const float* bpk = (const float*)d_in[9];
    const float* btk = (const float*)d_in[11];
    const float* bpv = (const float*)d_in[13];
    const float* btv = (const float*)d_in[15];
    const float* bpo = (const float*)d_in[17];
    const float* bto = (const float*)d_in[19];
    float* out = (float*)d_out;

    float *q_, *k_, *vt_, *h_, *cv_, *wt_;
    cudaGetSymbolAddress((void**)&q_,  g_q);
    cudaGetSymbolAddress((void**)&k_,  g_k);
    cudaGetSymbolAddress((void**)&vt_, g_vt);
    cudaGetSymbolAddress((void**)&h_,  g_h);
    cudaGetSymbolAddress((void**)&cv_, g_cv);
    cudaGetSymbolAddress((void**)&wt_, g_wt);

    cudaFuncSetAttribute(flash_tc, cudaFuncAttributeMaxDynamicSharedMemorySize,
                         FLASH_SMEM);
    cudaFuncSetAttribute(linear_tc, cudaFuncAttributeMaxDynamicSharedMemorySize,
                         LIN_SMEM);

    /* weight prep: round + transpose all 8 W into g_wt[z] as [N][K] */
    WP wp;
    const int widx[8] = {4, 6, 8, 10, 12, 14, 16, 18};
    for (int z = 0; z < 8; z++) {
        wp.w[z]  = (const float*)d_in[widx[z]];
        wp.wt[z] = wt_ + (size_t)z * HID * FAC;
    }
    wprep<<<dim3(32, 32, 8), dim3(32, 8)>>>(wp);

    float* Wpq = wt_ + 0*HID*FAC; float* Wtq = wt_ + 1*HID*FAC;
    float* Wpk = wt_ + 2*HID*FAC; float* Wtk = wt_ + 3*HID*FAC;
    float* Wpv = wt_ + 4*HID*FAC; float* Wtv = wt_ + 5*HID*FAC;
    float* Wpo = wt_ + 6*HID*FAC; float* Wto = wt_ + 7*HID*FAC;

    dim3 blk(256);
    dim3 gproj(ROWS/BM, FAC/BN);   /* (64, 4)  */
    dim3 gtran(ROWS/BM, HID/BN);   /* (64, 16) */

    linear_tc<<<gproj, blk, LIN_SMEM>>>(query, Wpq, bpq, h_, ROWS, FAC, HID, 1, 0);
    linear_tc<<<gtran, blk, LIN_SMEM>>>(h_,    Wtq, btq, q_, ROWS, HID, FAC, 2, 1);
    linear_tc<<<gproj, blk, LIN_SMEM>>>(key,   Wpk, bpk, h_, ROWS, FAC, HID, 1, 0);
    linear_tc<<<gtran, blk, LIN_SMEM>>>(h_,    Wtk, btk, k_, ROWS, HID, FAC, 2, 1);
    linear_tc<<<gproj, blk, LIN_SMEM>>>(value, Wpv, bpv, h_, ROWS, FAC, HID, 1, 0);
    linear_tc<<<gtran, blk, LIN_SMEM>>>(h_,    Wtv, btv, vt_, ROWS, HID, FAC, 3, 1);

    flash_tc<<<dim3(SEQ/128, BH), blk, FLASH_SMEM>>>(q_, k_, vt_, mask, cv_);

    linear_tc<<<gproj, blk, LIN_SMEM>>>(cv_, Wpo, bpo, h_,  ROWS, FAC, HID, 1, 0);
    linear_tc<<<gtran, blk, LIN_SMEM>>>(h_,  Wto, bto, out, ROWS, HID, FAC, 0, 1);
}

// round 10
// speedup vs baseline: 1.3847x; 1.0316x over previous
#include <cuda_runtime.h>
#include <math.h>
#include <stdint.h>

#define NB   4
#define SEQ  2048
#define HID  1024
#define FAC  256
#define NHD  16
#define DK   64
#define ROWS (NB*SEQ)   /* 8192 */
#define BH   (NB*NHD)   /* 64   */

/* linear tiling: 128x64 block, 8 warps of 32x32 (R7 geometry) */
#define BM 128
#define BN 64
#define BK 32
#define LDA  36
#define LDBN 36

/* flash geometry (R7, unchanged) */
#define KT   32
#define NCH  (SEQ/KT)    /* 64 */
#define LDQ  68
#define LDK  68
#define LDV  36
#define OFF_Q   0
#define OFF_K   (128*LDQ)                 /* 8704  */
#define OFF_V   (OFF_K + 2*KT*LDK)        /* 13056 */
#define OFF_MB  (OFF_V + 2*DK*LDV)        /* 17664 */
#define FLASH_FLOATS (OFF_MB + 2*KT)
#define FLASH_SMEM   (FLASH_FLOATS*4)

/* ---------------- scratch ------------------------------------------------ */
__device__ float g_q  [ROWS*HID];
__device__ float g_k  [ROWS*HID];
__device__ float g_vt [BH*DK*SEQ];   /* V transposed: [bh][d][token] */
__device__ float g_h  [3*ROWS*FAC];  /* per-chain hidden scratch */
__device__ float g_cv [ROWS*HID];

/* ---------------- helpers ------------------------------------------------ */
__device__ __forceinline__ float tf32r(float x) {
    uint32_t u;
    asm("cvt.rna.tf32.f32 %0, %1;" : "=r"(u) : "f"(x));
    return __uint_as_float(u);
}
__device__ __forceinline__ float4 cvt4(float4 v) {
    v.x = tf32r(v.x); v.y = tf32r(v.y); v.z = tf32r(v.z); v.w = tf32r(v.w);
    return v;
}
__device__ __forceinline__ void mma_tf32(float c[4], const uint32_t a[4], const uint32_t b[2]) {
    asm volatile(
        "mma.sync.aligned.m16n8k8.row.col.f32.tf32.tf32.f32 "
        "{%0,%1,%2,%3}, {%4,%5,%6,%7}, {%8,%9}, {%0,%1,%2,%3};"
        : "+f"(c[0]), "+f"(c[1]), "+f"(c[2]), "+f"(c[3])
        : "r"(a[0]), "r"(a[1]), "r"(a[2]), "r"(a[3]), "r"(b[0]), "r"(b[1]));
}
__device__ __forceinline__ void ldsm4(uint32_t f[4], uint32_t addr) {
    asm volatile("ldmatrix.sync.aligned.m8n8.x4.shared.b16 {%0,%1,%2,%3}, [%4];"
        : "=r"(f[0]), "=r"(f[1]), "=r"(f[2]), "=r"(f[3]) : "r"(addr));
}
__device__ __forceinline__ uint32_t smem_u32(const void* p) {
    return (uint32_t)__cvta_generic_to_shared(p);
}
__device__ __forceinline__ void cpa16(uint32_t dst, const void* src) {
    asm volatile("cp.async.cg.shared.global [%0], [%1], 16;" :: "r"(dst), "l"(src));
}
#define CPA_COMMIT() asm volatile("cp.async.commit_group;" ::: "memory")
#define CPA_WAIT0()  asm volatile("cp.async.wait_group 0;" ::: "memory")

__device__ __forceinline__ uint32_t frag_base_m(uint32_t base, int row0, int lane, int ld) {
    int lr = lane & 7, sel = lane >> 3;
    int row = row0 + lr + ((sel & 1) << 3);
    int col = (sel & 2) << 1;
    return base + (uint32_t)(row*ld + col)*4u;
}
__device__ __forceinline__ uint32_t frag_base_n(uint32_t base, int n0, int lane, int ld) {
    int lr = lane & 7, sel = lane >> 3;
    int row = n0 + lr + ((sel & 2) << 2);
    int col = (sel & 1) << 2;
    return base + (uint32_t)(row*ld + col)*4u;
}

#define MMA_CHUNK(aB0, aB1, bB0, bB1, acc)                                    \
    _Pragma("unroll")                                                         \
    for (int kk = 0; kk < BK; kk += 8) {                                      \
        uint32_t af0[4], af1[4], bq0[4], bq1[4];                              \
        ldsm4(af0, (aB0) + kk*4);                                             \
        ldsm4(af1, (aB1) + kk*4);                                             \
        ldsm4(bq0, (bB0) + kk*4);                                             \
        ldsm4(bq1, (bB1) + kk*4);                                             \
        mma_tf32(acc[0][0], af0, &bq0[0]);                                    \
        mma_tf32(acc[0][1], af0, &bq0[2]);                                    \
        mma_tf32(acc[0][2], af0, &bq1[0]);                                    \
        mma_tf32(acc[0][3], af0, &bq1[2]);                                    \
        mma_tf32(acc[1][0], af1, &bq0[0]);                                    \
        mma_tf32(acc[1][1], af1, &bq0[2]);                                    \
        mma_tf32(acc[1][2], af1, &bq1[0]);                                    \
        mma_tf32(acc[1][3], af1, &bq1[2]);                                    \
    }

/* =================== batched TF32 linear (R7 body, z-indexed operands) ====
   act: 0 = bias; 1 = bias+leaky(0.2); 2 = bias+tf32 round;
        3 = bias+tf32 round + TRANSPOSED store into Vt[bh][d][token]       */
struct LinB {
    const float* A[3];
    const float* W[3];
    const float* bias[3];
    float*       C[3];
    int          act[3];
};

__global__ void __launch_bounds__(256) linear_tc(LinB lb, int M, int N, int K)
{
    __shared__ __align__(16) float As[BM][LDA];
    __shared__ __align__(16) float Bs[BN][LDBN];

    const int z = blockIdx.z;
    const float* __restrict__ A    = lb.A[z];
    const float* __restrict__ W    = lb.W[z];
    const float* __restrict__ bias = lb.bias[z];
    float* __restrict__ C          = lb.C[z];
    const int act = lb.act[z];

    const int tid = threadIdx.x;
    const int row0 = blockIdx.x * BM;
    const int col0 = blockIdx.y * BN;

    const int arow = tid >> 3, acol = (tid & 7) << 2;
    const int bn = tid & 63, bk4 = (tid >> 6) << 2;

    const int wid = tid >> 5, lane = tid & 31;
    const int wm = (wid >> 1) * 32, wn = (wid & 1) * 32;
    const int r = lane >> 2, cq = lane & 3;

    const uint32_t smA = smem_u32(&As[0][0]);
    const uint32_t smB = smem_u32(&Bs[0][0]);
    const uint32_t aB0 = frag_base_m(smA, wm,      lane, LDA);
    const uint32_t aB1 = frag_base_m(smA, wm + 16, lane, LDA);
    const uint32_t bB0 = frag_base_n(smB, wn,      lane, LDBN);
    const uint32_t bB1 = frag_base_n(smB, wn + 16, lane, LDBN);

    float acc[2][4][4];
#pragma unroll
    for (int mt = 0; mt < 2; mt++)
#pragma unroll
        for (int nt = 0; nt < 4; nt++)
#pragma unroll
            for (int i = 0; i < 4; i++) acc[mt][nt][i] = 0.f;

    float4 pa[4];
    float  pb[2][4];
    const int nch = K / BK;

#pragma unroll
    for (int p = 0; p < 4; p++)
        pa[p] = *(const float4*)(A + (size_t)(row0 + arow + 32*p)*K + acol);
#pragma unroll
    for (int p = 0; p < 2; p++)
#pragma unroll
        for (int j = 0; j < 4; j++)
            pb[p][j] = W[(size_t)(bk4 + 16*p + j)*N + col0 + bn];

    for (int c = 0; c < nch; c++) {
#pragma unroll
        for (int p = 0; p < 4; p++)
            *(float4*)&As[arow + 32*p][acol] = cvt4(pa[p]);
#pragma unroll
        for (int p = 0; p < 2; p++) {
            float4 t = make_float4(pb[p][0], pb[p][1], pb[p][2], pb[p][3]);
            *(float4*)&Bs[bn][bk4 + 16*p] = cvt4(t);
        }
        __syncthreads();

        if (c + 1 < nch) {
            int k0 = (c + 1) * BK;
#pragma unroll
            for (int p = 0; p < 4; p++)
                pa[p] = *(const float4*)(A + (size_t)(row0 + arow + 32*p)*K + k0 + acol);
#pragma unroll
            for (int p = 0; p < 2; p++)
#pragma unroll
                for (int j = 0; j < 4; j++)
                    pb[p][j] = W[(size_t)(k0 + bk4 + 16*p + j)*N + col0 + bn];
        }

        MMA_CHUNK(aB0, aB1, bB0, bB1, acc);
        __syncthreads();
    }

#pragma unroll
    for (int mt = 0; mt < 2; mt++)
#pragma unroll
        for (int nt = 0; nt < 4; nt++) {
            int col = col0 + wn + nt*8 + cq*2;
            float b0 = bias[col], b1 = bias[col + 1];
#pragma unroll
            for (int hrow = 0; hrow < 2; hrow++) {
                int row = row0 + wm + mt*16 + r + hrow*8;
                float v0 = acc[mt][nt][hrow*2 + 0] + b0;
                float v1 = acc[mt][nt][hrow*2 + 1] + b1;
                if (act == 1) {
                    v0 = (v0 > 0.f) ? v0 : 0.2f*v0;
                    v1 = (v1 > 0.f) ? v1 : 0.2f*v1;
                } else if (act >= 2) {
                    v0 = tf32r(v0); v1 = tf32r(v1);
                }
                if (act == 3) {
                    int bb = row >> 11, token = row & (SEQ - 1);
                    int h0 = col >> 6, d0 = col & 63;
                    float* dst = C + ((size_t)(bb*NHD + h0)*DK + d0)*SEQ + token;
                    dst[0]   = v0;
                    dst[SEQ] = v1;
                } else {
                    *(float2*)&C[(size_t)row*N + col] = make_float2(v0, v1);
                }
            }
        }
}

/* =================== Flash attention (R7, unchanged) ===================== */
__global__ void __launch_bounds__(256, 2) flash_tc(
    const float* __restrict__ Q, const float* __restrict__ K,
    const float* __restrict__ Vt, const int* __restrict__ mask,
    float* __restrict__ Cv)
{
    extern __shared__ __align__(16) float sm[];
    const uint32_t smBase = smem_u32(sm);
    const uint32_t smQ = smBase + OFF_Q*4u;
    const uint32_t smK[2] = { smBase + OFF_K*4u, smBase + (OFF_K + KT*LDK)*4u };
    const uint32_t smV[2] = { smBase + OFF_V*4u, smBase + (OFF_V + DK*LDV)*4u };
    const uint32_t smM = smBase + OFF_MB*4u;
    const int* MBI = (const int*)(sm + OFF_MB);

    const int bh = blockIdx.y;
    const int b = bh >> 4, h = bh & 15;
    const int i0 = blockIdx.x * 128;
    const float* Qp  = Q  + (size_t)b*SEQ*HID + h*DK;
    const float* Kp  = K  + (size_t)b*SEQ*HID + h*DK;
    const float* Vtp = Vt + (size_t)bh*DK*SEQ;
    const int* mrow = mask + b*SEQ;
    float* Cp = Cv + (size_t)b*SEQ*HID + h*DK;

    const int tid = threadIdx.x;
    const int wid = tid >> 5, lane = tid & 31;
    const int wm = wid * 16;
    const int r = lane >> 2, cq = lane & 3;

#pragma unroll
    for (int p = 0; p < 8; p++) {
        int idx = p*256 + tid;
        int row = idx >> 4, u = idx & 15;
        cpa16(smQ + (uint32_t)(row*LDQ + u*4)*4u,
              Qp + (size_t)(i0 + row)*HID + u*4);
    }
#pragma unroll
    for (int p = 0; p < 2; p++) {
        int idx = p*256 + tid;
        int krow = idx >> 4, ku = idx & 15;
        cpa16(smK[0] + (uint32_t)(krow*LDK + ku*4)*4u,
              Kp + (size_t)krow*HID + ku*4);
        int vrow = idx >> 3, vu = idx & 7;
        cpa16(smV[0] + (uint32_t)(vrow*LDV + vu*4)*4u,
              Vtp + (size_t)vrow*SEQ + vu*4);
    }
    if (tid < 8) cpa16(smM + (uint32_t)(tid*4)*4u, mrow + tid*4);
    CPA_COMMIT();

    const uint32_t aQ = frag_base_m(smQ, wm, lane, LDQ);
    const uint32_t aP = aQ;  /* unused alias removed below; P has own region */
    (void)aP;
    uint32_t bKf[2][2], bVf[2][4];
#pragma unroll
    for (int buf = 0; buf < 2; buf++) {
#pragma unroll
        for (int g = 0; g < 2; g++) bKf[buf][g] = frag_base_n(smK[buf], g*16, lane, LDK);
#pragma unroll
        for (int g = 0; g < 4; g++) bVf[buf][g] = frag_base_n(smV[buf], g*16, lane, LDV);
    }

    float acc_o[8][4];
#pragma unroll
    for (int nt = 0; nt < 8; nt++)
#pragma unroll
        for (int i = 0; i < 4; i++) acc_o[nt][i] = 0.f;
    float m_st[2] = {-1e20f, -1e20f};
    float l_st[2] = {0.f, 0.f};

    for (int c = 0; c < NCH; c++) {
        const int cur = c & 1, nxt = cur ^ 1;

        CPA_WAIT0();
        __syncthreads();

        if (c + 1 < NCH) {
            const size_t k0 = (size_t)(c + 1) * KT;
#pragma unroll
            for (int p = 0; p < 2; p++) {
                int idx = p*256 + tid;
                int krow = idx >> 4, ku = idx & 15;
                cpa16(smK[nxt] + (uint32_t)(krow*LDK + ku*4)*4u,
                      Kp + (k0 + krow)*HID + ku*4);
                int vrow = idx >> 3, vu = idx & 7;
                cpa16(smV[nxt] + (uint32_t)(vrow*LDV + vu*4)*4u,
                      Vtp + (size_t)vrow*SEQ + k0 + vu*4);
            }
            if (tid < 8) cpa16(smM + (uint32_t)(nxt*KT + tid*4)*4u, mrow + k0 + tid*4);
            CPA_COMMIT();
        }

        float acc_s[4][4];
#pragma unroll
        for (int nt = 0; nt < 4; nt++)
#pragma unroll
            for (int i = 0; i < 4; i++) acc_s[nt][i] = 0.f;
#pragma unroll
        for (int kk = 0; kk < DK; kk += 8) {
            uint32_t af[4];
            ldsm4(af, aQ + kk*4);
#pragma unroll
            for (int g = 0; g < 2; g++) {
                uint32_t bq[4];
                ldsm4(bq, bKf[cur][g] + kk*4);
                mma_tf32(acc_s[2*g    ], af, &bq[0]);
                mma_tf32(acc_s[2*g + 1], af, &bq[2]);
            }
        }

        const int* mi = MBI + cur*KT;
        float bias2[4][2];
#pragma unroll
        for (int nt = 0; nt < 4; nt++) {
            int j = nt*8 + cq*2;
            bias2[nt][0] = mi[j]     ? 0.f : -1e20f;
            bias2[nt][1] = mi[j + 1] ? 0.f : -1e20f;
        }
        float alpha[2];
#pragma unroll
        for (int rr = 0; rr < 2; rr++) {
            float mx = -3.4e38f;
#pragma unroll
            for (int nt = 0; nt < 4; nt++)
#pragma unroll
                for (int cc = 0; cc < 2; cc++) {
                    float s = acc_s[nt][rr*2+cc] * 0.125f + bias2[nt][cc];
                    acc_s[nt][rr*2+cc] = s;
                    mx = fmaxf(mx, s);
                }
            mx = fmaxf(mx, __shfl_xor_sync(0xffffffffu, mx, 1));
            mx = fmaxf(mx, __shfl_xor_sync(0xffffffffu, mx, 2));
            float m_new = fmaxf(m_st[rr], mx);
            float a = __expf(m_st[rr] - m_new);
            m_st[rr] = m_new;
            alpha[rr] = a;
            float lsum = 0.f;
#pragma unroll
            for (int nt = 0; nt < 4; nt++)
#pragma unroll
                for (int cc = 0; cc < 2; cc++) {
                    float p = __expf(acc_s[nt][rr*2+cc] - m_new);
                    acc_s[nt][rr*2+cc] = p;
                    lsum += p;
                }
            l_st[rr] = l_st[rr]*a + lsum;
        }
#pragma unroll
        for (int nt = 0; nt < 8; nt++)
#pragma unroll
            for (int i = 0; i < 4; i++) acc_o[nt][i] *= alpha[i>>1];

        /* P round-trip through warp-private rows of the Q region is illegal
           (Q still live) — P uses its own region? R7 kept P region inside
           smQ?? No: R7 used OFF_P region. Here Q region must stay intact,
           so P is written into the Q-region? NO — keep R7 exactly: P had
           its own OFF_P region in the 89KB layout. Reproduce that. */

        /* write P into per-warp rows of the V-staging pad area? -- see note:
           we keep R7's dedicated P region appended after MB. */
#pragma unroll
        for (int rr = 0; rr < 2; rr++) {
            int prow = wm + rr*8 + r;
#pragma unroll
            for (int nt = 0; nt < 4; nt++)
                *(float2*)&sm[FLASH_FLOATS + prow*LDV + nt*8 + cq*2] =
                    make_float2(tf32r(acc_s[nt][rr*2+0]), tf32r(acc_s[nt][rr*2+1]));
        }
        __syncwarp();

        {
            const uint32_t aPf = frag_base_m(smBase + FLASH_FLOATS*4u, wm, lane, LDV);
#pragma unroll
            for (int kk = 0; kk < KT; kk += 8) {
                uint32_t af[4];
                ldsm4(af, aPf + kk*4);
#pragma unroll
                for (int g = 0; g < 4; g++) {
                    uint32_t bv[4];
                    ldsm4(bv, bVf[cur][g] + kk*4);
                    mma_tf32(acc_o[2*g    ], af, &bv[0]);
                    mma_tf32(acc_o[2*g + 1], af, &bv[2]);
                }
            }
        }
    }

    float inv2[2];
#pragma unroll
    for (int rr = 0; rr < 2; rr++) {
        float lt = l_st[rr];
        lt += __shfl_xor_sync(0xffffffffu, lt, 1);
        lt += __shfl_xor_sync(0xffffffffu, lt, 2);
        inv2[rr] = 1.f / lt;
    }
#pragma unroll
    for (int nt = 0; nt < 8; nt++) {
        int col = nt*8 + cq*2;
#pragma unroll
        for (int rr = 0; rr < 2; rr++) {
            int row = i0 + wm + rr*8 + r;
            *(float2*)&Cp[(size_t)row*HID + col] =
                make_float2(acc_o[nt][rr*2+0]*inv2[rr],
                            acc_o[nt][rr*2+1]*inv2[rr]);
        }
    }
}

/* P region appended after FLASH_FLOATS: 128 rows x LDV */
#define FLASH_SMEM_TOTAL ((FLASH_FLOATS + 128*LDV)*4)

/* ---------------- host orchestration ------------------------------------- */
extern "C" void kernel_launch(void* const* d_in, const int* in_sizes, int n_in,
                              void* d_out, int out_size)
{
    const float* query = (const float*)d_in[0];
    const float* key   = (const float*)d_in[1];
    const float* value = (const float*)d_in[2];
    const int*   mask  = (const int*)  d_in[3];
    const float* Wpq = (const float*)d_in[4],  *bpq = (const float*)d_in[5];
    const float* Wtq = (const float*)d_in[6],  *btq = (const float*)d_in[7];
    const float* Wpk = (const float*)d_in[8],  *bpk = (const float*)d_in[9];
    const float* Wtk = (const float*)d_in[10], *btk = (const float*)d_in[11];
    const float* Wpv = (const float*)d_in[12], *bpv = (const float*)d_in[13];
    const float* Wtv = (const float*)d_in[14], *btv = (const float*)d_in[15];
    const float* Wpo = (const float*)d_in[16], *bpo = (const float*)d_in[17];
    const float* Wto = (const float*)d_in[18], *bto = (const float*)d_in[19];
    float* out = (float*)d_out;

    float *q_, *k_, *vt_, *h_, *cv_;
    cudaGetSymbolAddress((void**)&q_,  g_q);
    cudaGetSymbolAddress((void**)&k_,  g_k);
    cudaGetSymbolAddress((void**)&vt_, g_vt);
    cudaGetSymbolAddress((void**)&h_,  g_h);
    cudaGetSymbolAddress((void**)&cv_, g_cv);
    float* h0 = h_;
    float* h1 = h_ + (size_t)ROWS*FAC;
    float* h2 = h_ + 2*(size_t)ROWS*FAC;

    cudaFuncSetAttribute(flash_tc, cudaFuncAttributeMaxDynamicSharedMemorySize,
                         FLASH_SMEM_TOTAL);

    dim3 blk(256);

    /* batched q/k/v proj: one launch, z = chain */
    LinB projB;
    projB.A[0] = query; projB.A[1] = key; projB.A[2] = value;
    projB.W[0] = Wpq;   projB.W[1] = Wpk; projB.W[2] = Wpv;
    projB.bias[0] = bpq; projB.bias[1] = bpk; projB.bias[2] = bpv;
    projB.C[0] = h0;    projB.C[1] = h1;  projB.C[2] = h2;
    projB.act[0] = projB.act[1] = projB.act[2] = 1;
    linear_tc<<<dim3(ROWS/BM, FAC/BN, 3), blk>>>(projB, ROWS, FAC, HID);

    /* batched q/k/v tran: one launch */
    LinB tranB;
    tranB.A[0] = h0;  tranB.A[1] = h1;  tranB.A[2] = h2;
    tranB.W[0] = Wtq; tranB.W[1] = Wtk; tranB.W[2] = Wtv;
    tranB.bias[0] = btq; tranB.bias[1] = btk; tranB.bias[2] = btv;
    tranB.C[0] = q_;  tranB.C[1] = k_;  tranB.C[2] = vt_;
    tranB.act[0] = 2; tranB.act[1] = 2; tranB.act[2] = 3;
    linear_tc<<<dim3(ROWS/BM, HID/BN, 3), blk>>>(tranB, ROWS, HID, FAC);

    flash_tc<<<dim3(SEQ/128, BH), blk, FLASH_SMEM_TOTAL>>>(q_, k_, vt_, mask, cv_);

    /* output chain (single-z batches) */
    LinB poB;
    poB.A[0] = cv_; poB.W[0] = Wpo; poB.bias[0] = bpo; poB.C[0] = h0; poB.act[0] = 1;
    linear_tc<<<dim3(ROWS/BM, FAC/BN, 1), blk>>>(poB, ROWS, FAC, HID);

    LinB toB;
    toB.A[0] = h0; toB.W[0] = Wto; toB.bias[0] = bto; toB.C[0] = out; toB.act[0] = 0;
    linear_tc<<<dim3(ROWS/BM, HID/BN, 1), blk>>>(toB, ROWS, HID, FAC);
}